// round 12
// baseline (speedup 1.0000x reference)
#include <cuda_runtime.h>
#include <stdint.h>

// x, y : (B=2, C=32, H=80, W=240) float32
// out  : (B=2, 64, 64, 80, 240) float32
//   out[b, c,    d, h, w] = x[b, c,    h, w]   * (w >= d)   c < 32
//   out[b, c,    d, h, w] = y[b, c-32, h, w-d] * (w >= d)   c >= 32
//
// One CTA = one (b, c, h-PAIR); all 64 disparities for BOTH halves.
// Store footprint per (d, half): 1920 B = exactly 15 x 128 B lines,
// 128B-aligned (76800 and 1920 are both multiples of 128) -> no cache line
// is ever split between CTAs; every line is fully written within one loop
// iteration -> pure full-line write stream to DRAM (no RMW).

#define Bn 2
#define Cn 32
#define Dn 64
#define Hn 80
#define Wn 240
#define W4 (Wn / 4)      // 60
#define HW (Hn * Wn)     // 19200
#define HW4 (HW / 4)     // 4800 float4 per disparity slice

// De-interleaved y rows: ysm[r][j][i] = y_row_r[i*4 + j]. Gather at linear
// idx -> ysm[r][idx&3][idx>>2]; lane stride 4 in idx -> conflict-free banks.
#define YSM(r, idx) ysm[r][(idx) & 3][(idx) >> 2]

// block = (120, 8): tx spans 120 float4 of the h-pair chunk, ty = d group
// grid  = (Hn/2, Cn, Bn)
__global__ __launch_bounds__(960) void cost_volume_kernel(
    const float* __restrict__ x,
    const float* __restrict__ y,
    float* __restrict__ out)
{
    __shared__ float ysm[2][4][64];

    const unsigned tx = threadIdx.x;   // 0..119
    const unsigned ty = threadIdx.y;   // 0..7
    const unsigned h2 = blockIdx.x;    // 0..39 (h pair)
    const unsigned c  = blockIdx.y;
    const unsigned b  = blockIdx.z;

    const unsigned sub = (tx >= 60u) ? 1u : 0u;   // row within pair
    const unsigned w4  = tx - 60u * sub;          // 0..59
    const unsigned h   = h2 * 2u + sub;

    const unsigned row_in = ((b * Cn + c) * Hn + h) * Wn;  // fits u32

    if (ty == 0) {
        // 120 threads load the two y rows (60 float4 each), de-interleaved
        float4 yv = reinterpret_cast<const float4*>(y + row_in)[w4];
        ysm[sub][0][w4] = yv.x;
        ysm[sub][1][w4] = yv.y;
        ysm[sub][2][w4] = yv.z;
        ysm[sub][3][w4] = yv.w;
    }
    const float4 xv = reinterpret_cast<const float4*>(x + row_in)[w4];
    __syncthreads();

    const int w  = (int)(w4 * 4u);
    const int d0 = (int)(ty * 8u);

    // chunk base in float4 units: pair chunk is contiguous, so +tx addresses
    // both rows (tx<60 -> h_lo, tx>=60 -> h_hi)
    const unsigned baseL4 = (((b * 2u * Cn + c) * Dn + (unsigned)d0) * Hn
                             + h2 * 2u) * (unsigned)W4 + tx;
    float4* oL = reinterpret_cast<float4*>(out) + baseL4;
    float4* oR = oL + (unsigned)(Cn * Dn) * HW4;

    // Sliding window on this thread's own row
    const int i0 = w - d0;
    float r0 = (i0     >= 0) ? YSM(sub, i0    ) : 0.0f;
    float r1 = (i0 + 1 >= 0) ? YSM(sub, i0 + 1) : 0.0f;
    float r2 = (i0 + 2 >= 0) ? YSM(sub, i0 + 2) : 0.0f;
    float r3 = (i0 + 3 >= 0) ? YSM(sub, i0 + 3) : 0.0f;

#pragma unroll
    for (int k = 0; k < 8; ++k) {
        const int d = d0 + k;

        float4 l = xv;
        if (w     < d) l.x = 0.0f;
        if (w + 1 < d) l.y = 0.0f;
        if (w + 2 < d) l.z = 0.0f;
        if (w + 3 < d) l.w = 0.0f;

        __stcs(oL, l);
        __stcs(oR, make_float4(r0, r1, r2, r3));
        oL += HW4;
        oR += HW4;

        const int ni = w - d - 1;
        r3 = r2; r2 = r1; r1 = r0;
        r0 = (ni >= 0) ? YSM(sub, ni) : 0.0f;
    }
}

extern "C" void kernel_launch(void* const* d_in, const int* in_sizes, int n_in,
                              void* d_out, int out_size)
{
    const float* x = (const float*)d_in[0];
    const float* y = (const float*)d_in[1];
    float* out = (float*)d_out;

    dim3 block(120, 8);           // 960 threads = 30 warps
    dim3 grid(Hn / 2, Cn, Bn);    // 40 x 32 x 2 = 2560 CTAs
    cost_volume_kernel<<<grid, block>>>(x, y, out);
}